// round 5
// baseline (speedup 1.0000x reference)
#include <cuda_runtime.h>
#include <cuda_bf16.h>
#include <cstdint>

#define N_NODES 16384
#define DIM 512
#define SEG_CAP 64
#define GEMM_BLOCKS 512

// Scratch
__device__ float         g_Yf   [(size_t)N_NODES * DIM];
__device__ __nv_bfloat16 g_Ybf  [(size_t)N_NODES * DIM];
__device__ uint16_t      g_lists[(size_t)N_NODES * 512];   // 8 segs x 64 per row
__device__ int           g_cnt  [(size_t)N_NODES * 8];

__device__ __forceinline__ uint32_t f2tf32(float f) {
    uint32_t u;
    asm("cvt.rna.tf32.f32 %0, %1;" : "=r"(u) : "f"(f));
    return u;
}
__device__ __forceinline__ float bf_lo(uint32_t r) {
    uint32_t o; asm("prmt.b32 %0, %1, %2, 0x1044;" : "=r"(o) : "r"(r), "r"(0u));
    return __uint_as_float(o);
}
__device__ __forceinline__ float bf_hi(uint32_t r) {
    uint32_t o; asm("prmt.b32 %0, %1, %2, 0x3244;" : "=r"(o) : "r"(r), "r"(0u));
    return __uint_as_float(o);
}

// ---------------------------------------------------------------------------
// Kernel F: role-split fused kernel.
//   blocks [0, 512):       Y = x @ W  (tf32 mma.sync, R2-proven code)
//   blocks [512, 16896):   scan A row (blockIdx-512), ballot-compact nonzero
//                          col indices into g_lists / g_cnt (per-warp segments)
// Roles use complementary resources (tensor+smem vs DRAM stream) -> overlap.
// ---------------------------------------------------------------------------
union SmemF {
    struct { float As[128][36]; float Bs[32][132]; } g;   // 35328 bytes
    struct { uint16_t idx[8 * SEG_CAP]; int cnt[8]; } s;
};

__global__ void __launch_bounds__(256, 2) fused_gemm_scan(const float* __restrict__ x,
                                                          const float* __restrict__ W,
                                                          const float* __restrict__ A) {
    __shared__ SmemF u;
    const int tid  = threadIdx.x;
    const int wid  = tid >> 5;
    const int lane = tid & 31;

    if (blockIdx.x < GEMM_BLOCKS) {
        // ================= GEMM role =================
        const int wm   = wid & 3;
        const int wn   = wid >> 2;
        const int g    = lane >> 2;
        const int tg   = lane & 3;
        const int m0 = (blockIdx.x >> 2) * 128;
        const int n0 = (blockIdx.x & 3) * 128;

        float c[2][8][4];
#pragma unroll
        for (int i = 0; i < 2; i++)
#pragma unroll
            for (int j = 0; j < 8; j++)
#pragma unroll
                for (int k = 0; k < 4; k++) c[i][j][k] = 0.f;

        for (int kt = 0; kt < DIM; kt += 32) {
#pragma unroll
            for (int l = 0; l < 4; l++) {
                int lin = (l * 256 + tid) * 4;
                int m = lin >> 5, kk = lin & 31;
                float4 v = *(const float4*)(x + (size_t)(m0 + m) * DIM + kt + kk);
                u.g.As[m][kk + 0] = __uint_as_float(f2tf32(v.x));
                u.g.As[m][kk + 1] = __uint_as_float(f2tf32(v.y));
                u.g.As[m][kk + 2] = __uint_as_float(f2tf32(v.z));
                u.g.As[m][kk + 3] = __uint_as_float(f2tf32(v.w));
            }
#pragma unroll
            for (int l = 0; l < 4; l++) {
                int lin = (l * 256 + tid) * 4;
                int kk = lin >> 7, n = lin & 127;
                float4 v = *(const float4*)(W + (size_t)(kt + kk) * DIM + n0 + n);
                u.g.Bs[kk][n + 0] = __uint_as_float(f2tf32(v.x));
                u.g.Bs[kk][n + 1] = __uint_as_float(f2tf32(v.y));
                u.g.Bs[kk][n + 2] = __uint_as_float(f2tf32(v.z));
                u.g.Bs[kk][n + 3] = __uint_as_float(f2tf32(v.w));
            }
            __syncthreads();

#pragma unroll
            for (int ks = 0; ks < 4; ks++) {
                const int kb = ks * 8;
                uint32_t a[2][4], b[8][2];
#pragma unroll
                for (int mi = 0; mi < 2; mi++) {
                    int r = wm * 32 + mi * 16;
                    a[mi][0] = __float_as_uint(u.g.As[r + g    ][kb + tg    ]);
                    a[mi][1] = __float_as_uint(u.g.As[r + g + 8][kb + tg    ]);
                    a[mi][2] = __float_as_uint(u.g.As[r + g    ][kb + tg + 4]);
                    a[mi][3] = __float_as_uint(u.g.As[r + g + 8][kb + tg + 4]);
                }
#pragma unroll
                for (int ni = 0; ni < 8; ni++) {
                    int nn = wn * 64 + ni * 8 + g;
                    b[ni][0] = __float_as_uint(u.g.Bs[kb + tg    ][nn]);
                    b[ni][1] = __float_as_uint(u.g.Bs[kb + tg + 4][nn]);
                }
#pragma unroll
                for (int mi = 0; mi < 2; mi++)
#pragma unroll
                    for (int ni = 0; ni < 8; ni++) {
                        asm volatile(
                            "mma.sync.aligned.m16n8k8.row.col.f32.tf32.tf32.f32 "
                            "{%0,%1,%2,%3}, {%4,%5,%6,%7}, {%8,%9}, {%0,%1,%2,%3};"
                            : "+f"(c[mi][ni][0]), "+f"(c[mi][ni][1]),
                              "+f"(c[mi][ni][2]), "+f"(c[mi][ni][3])
                            : "r"(a[mi][0]), "r"(a[mi][1]), "r"(a[mi][2]), "r"(a[mi][3]),
                              "r"(b[ni][0]), "r"(b[ni][1]));
                    }
            }
            __syncthreads();
        }

#pragma unroll
        for (int mi = 0; mi < 2; mi++) {
#pragma unroll
            for (int ni = 0; ni < 8; ni++) {
                int row0 = m0 + wm * 32 + mi * 16 + g;
                int col  = n0 + wn * 64 + ni * 8 + tg * 2;
                float2 v01 = make_float2(c[mi][ni][0], c[mi][ni][1]);
                float2 v23 = make_float2(c[mi][ni][2], c[mi][ni][3]);
                *(float2*)(g_Yf + (size_t)row0 * DIM + col)       = v01;
                *(float2*)(g_Yf + (size_t)(row0 + 8) * DIM + col) = v23;
                __nv_bfloat162 h01, h23;
                h01.x = __float2bfloat16_rn(v01.x); h01.y = __float2bfloat16_rn(v01.y);
                h23.x = __float2bfloat16_rn(v23.x); h23.y = __float2bfloat16_rn(v23.y);
                *(__nv_bfloat162*)(g_Ybf + (size_t)row0 * DIM + col)       = h01;
                *(__nv_bfloat162*)(g_Ybf + (size_t)(row0 + 8) * DIM + col) = h23;
            }
        }
    } else {
        // ================= SCAN role =================
        const int row = blockIdx.x - GEMM_BLOCKS;
        const int w   = wid;
        const unsigned lml = (1u << lane) - 1u;

        const uint4* Ar = (const uint4*)(A + (size_t)row * N_NODES + w * 2048);
        int cnt = 0;
#pragma unroll 1
        for (int half = 0; half < 2; half++) {
            uint4 v[8];
#pragma unroll
            for (int k = 0; k < 8; k++)
                v[k] = __ldcs(Ar + (half * 8 + k) * 32 + lane);
#pragma unroll
            for (int k = 0; k < 8; k++) {
                unsigned nz  = v[k].x | v[k].y | v[k].z | v[k].w;
                unsigned any = __ballot_sync(0xFFFFFFFFu, nz != 0);
                if (any) {
                    int colbase = w * 2048 + ((half * 8 + k) * 32 + lane) * 4;
                    unsigned m;
                    m = __ballot_sync(0xFFFFFFFFu, v[k].x != 0);
                    if (v[k].x) { int p = cnt + __popc(m & lml); if (p < SEG_CAP) u.s.idx[w * SEG_CAP + p] = (uint16_t)(colbase + 0); }
                    cnt += __popc(m);
                    m = __ballot_sync(0xFFFFFFFFu, v[k].y != 0);
                    if (v[k].y) { int p = cnt + __popc(m & lml); if (p < SEG_CAP) u.s.idx[w * SEG_CAP + p] = (uint16_t)(colbase + 1); }
                    cnt += __popc(m);
                    m = __ballot_sync(0xFFFFFFFFu, v[k].z != 0);
                    if (v[k].z) { int p = cnt + __popc(m & lml); if (p < SEG_CAP) u.s.idx[w * SEG_CAP + p] = (uint16_t)(colbase + 2); }
                    cnt += __popc(m);
                    m = __ballot_sync(0xFFFFFFFFu, v[k].w != 0);
                    if (v[k].w) { int p = cnt + __popc(m & lml); if (p < SEG_CAP) u.s.idx[w * SEG_CAP + p] = (uint16_t)(colbase + 3); }
                    cnt += __popc(m);
                }
            }
        }
        __syncwarp();
        // copy segment (128 bytes) + count to global
        if (lane < 8) {
            const uint4* src = (const uint4*)(u.s.idx + w * SEG_CAP);
            uint4* dst = (uint4*)(g_lists + (size_t)row * 512 + w * SEG_CAP);
            dst[lane] = src[lane];
        }
        if (lane == 0)
            g_cnt[row * 8 + w] = (cnt < SEG_CAP) ? cnt : SEG_CAP;
    }
}

// ---------------------------------------------------------------------------
// Kernel G: gather + residual + bias + relu.
// One CTA per row; warp w processes its 64-entry segment (depth-2 pipelined
// full-row bf16 gathers); smem tree-reduce; epilogue.
// ---------------------------------------------------------------------------
__global__ void __launch_bounds__(256) gcn_gather(const float* __restrict__ deg,
                                                  const float* __restrict__ bias,
                                                  float* __restrict__ out) {
    __shared__ uint16_t s_idx[8 * SEG_CAP];
    __shared__ int      s_cnt[8];
    __shared__ float    s_part[8 * DIM];

    const int row  = blockIdx.x;
    const int tid  = threadIdx.x;
    const int w    = tid >> 5;
    const int lane = tid & 31;

    if (tid < 64) ((uint4*)s_idx)[tid] = ((const uint4*)(g_lists + (size_t)row * 512))[tid];
    if (tid < 8)  s_cnt[tid] = g_cnt[row * 8 + tid];
    __syncthreads();

    float acc[16];
#pragma unroll
    for (int i = 0; i < 16; i++) acc[i] = 0.f;

    {
        const int n = s_cnt[w];
        const uint16_t* myidx = s_idx + w * SEG_CAP;
        uint4 pa[2], pb[2];
        if (n > 0) {
            const uint4* yp = (const uint4*)(g_Ybf + (size_t)myidx[0] * DIM);
            pa[0] = yp[lane]; pb[0] = yp[32 + lane];
        }
        if (n > 1) {
            const uint4* yp = (const uint4*)(g_Ybf + (size_t)myidx[1] * DIM);
            pa[1] = yp[lane]; pb[1] = yp[32 + lane];
        }
#pragma unroll 2
        for (int k = 0; k < n; k++) {
            uint4 ca = pa[k & 1];
            uint4 cb = pb[k & 1];
            if (k + 2 < n) {
                const uint4* yp = (const uint4*)(g_Ybf + (size_t)myidx[k + 2] * DIM);
                pa[k & 1] = yp[lane];
                pb[k & 1] = yp[32 + lane];
            }
            acc[0]  += bf_lo(ca.x); acc[1]  += bf_hi(ca.x);
            acc[2]  += bf_lo(ca.y); acc[3]  += bf_hi(ca.y);
            acc[4]  += bf_lo(ca.z); acc[5]  += bf_hi(ca.z);
            acc[6]  += bf_lo(ca.w); acc[7]  += bf_hi(ca.w);
            acc[8]  += bf_lo(cb.x); acc[9]  += bf_hi(cb.x);
            acc[10] += bf_lo(cb.y); acc[11] += bf_hi(cb.y);
            acc[12] += bf_lo(cb.z); acc[13] += bf_hi(cb.z);
            acc[14] += bf_lo(cb.w); acc[15] += bf_hi(cb.w);
        }
    }

    {
        float* p0 = s_part + w * DIM + 8 * lane;
        *(float4*)(p0 + 0)       = make_float4(acc[0], acc[1], acc[2], acc[3]);
        *(float4*)(p0 + 4)       = make_float4(acc[4], acc[5], acc[6], acc[7]);
        *(float4*)(p0 + 256)     = make_float4(acc[8], acc[9], acc[10], acc[11]);
        *(float4*)(p0 + 256 + 4) = make_float4(acc[12], acc[13], acc[14], acc[15]);
    }
    __syncthreads();

    {
        const int col = tid * 2;
        float a0 = 0.f, a1 = 0.f;
#pragma unroll
        for (int ww = 0; ww < 8; ww++) {
            float2 p = *(const float2*)(s_part + ww * DIM + col);
            a0 += p.x; a1 += p.y;
        }
        const float di = 1.0f / deg[row];
        float2 ys = *(const float2*)(g_Yf + (size_t)row * DIM + col);
        float2 bb = *(const float2*)(bias + col);
        float o0 = fmaxf(di * a0 + (1.0f + di) * ys.x + bb.x, 0.f);
        float o1 = fmaxf(di * a1 + (1.0f + di) * ys.y + bb.y, 0.f);
        *(float2*)(out + (size_t)row * DIM + col) = make_float2(o0, o1);
    }
}

// ---------------------------------------------------------------------------
extern "C" void kernel_launch(void* const* d_in, const int* in_sizes, int n_in,
                              void* d_out, int out_size) {
    const float *x = nullptr, *A = nullptr, *deg = nullptr, *W = nullptr, *b = nullptr;
    for (int i = 0; i < n_in; i++) {
        long long sz = (long long)in_sizes[i];
        if      (sz == (long long)N_NODES * N_NODES) A   = (const float*)d_in[i];
        else if (sz == (long long)N_NODES * DIM)     x   = (const float*)d_in[i];
        else if (sz == (long long)DIM * DIM)         W   = (const float*)d_in[i];
        else if (sz == (long long)N_NODES)           deg = (const float*)d_in[i];
        else if (sz == (long long)DIM)               b   = (const float*)d_in[i];
    }

    fused_gemm_scan<<<GEMM_BLOCKS + N_NODES, 256>>>(x, W, A);
    gcn_gather<<<N_NODES, 256>>>(deg, b, (float*)d_out);
}

// round 9
// speedup vs baseline: 1.4564x; 1.4564x over previous
#include <cuda_runtime.h>
#include <cuda_bf16.h>
#include <cuda_fp16.h>
#include <cstdint>

#define N_NODES 16384
#define DIM 512
#define SEG_CAP 64

// Scratch
__device__ float         g_Yf [(size_t)N_NODES * DIM];
__device__ __nv_bfloat16 g_Ybf[(size_t)N_NODES * DIM];
__device__ __half        g_xh [(size_t)N_NODES * DIM];   // fp16 x
__device__ __half        g_Wh [(size_t)DIM * DIM];       // fp16 W^T [n][k]

__device__ __forceinline__ float bf_lo(uint32_t r) {
    uint32_t o; asm("prmt.b32 %0, %1, %2, 0x1044;" : "=r"(o) : "r"(r), "r"(0u));
    return __uint_as_float(o);
}
__device__ __forceinline__ float bf_hi(uint32_t r) {
    uint32_t o; asm("prmt.b32 %0, %1, %2, 0x3244;" : "=r"(o) : "r"(r), "r"(0u));
    return __uint_as_float(o);
}
__device__ __forceinline__ uint32_t smem_u32(const void* p) {
    uint32_t a;
    asm("{ .reg .u64 t; cvta.to.shared.u64 t, %1; cvt.u32.u64 %0, t; }" : "=r"(a) : "l"(p));
    return a;
}

#define CP_ASYNC16(saddr, gptr) \
    asm volatile("cp.async.cg.shared.global [%0], [%1], 16;" :: "r"(saddr), "l"(gptr) : "memory")
#define CP_COMMIT() asm volatile("cp.async.commit_group;" ::: "memory")
#define CP_WAIT2()  asm volatile("cp.async.wait_group 2;" ::: "memory")

#define LDMX4(r0, r1, r2, r3, addr) \
    asm volatile("ldmatrix.sync.aligned.m8n8.x4.shared.b16 {%0,%1,%2,%3}, [%4];" \
                 : "=r"(r0), "=r"(r1), "=r"(r2), "=r"(r3) : "r"(addr))

// ---------------------------------------------------------------------------
// Kernel 0a: g_xh = fp16(x)
// ---------------------------------------------------------------------------
__global__ void __launch_bounds__(256) xh_kernel(const float* __restrict__ x) {
    const size_t i = ((size_t)blockIdx.x * 256 + threadIdx.x) * 4;
    float4 v = *(const float4*)(x + i);
    __half2 h0 = __floats2half2_rn(v.x, v.y);
    __half2 h1 = __floats2half2_rn(v.z, v.w);
    uint2 pk;
    pk.x = *(uint32_t*)&h0;
    pk.y = *(uint32_t*)&h1;
    *(uint2*)(g_xh + i) = pk;
}

// ---------------------------------------------------------------------------
// Kernel 0b: g_Wh[n][k] = fp16(W[k][n])
// ---------------------------------------------------------------------------
__global__ void wt_kernel(const float* __restrict__ W) {
    __shared__ float t[32][33];
    const int bx = blockIdx.x * 32;   // n base
    const int by = blockIdx.y * 32;   // k base
    const int tx = threadIdx.x, ty = threadIdx.y;
#pragma unroll
    for (int i = ty; i < 32; i += 8)
        t[i][tx] = W[(size_t)(by + i) * DIM + bx + tx];
    __syncthreads();
#pragma unroll
    for (int i = ty; i < 32; i += 8)
        g_Wh[(size_t)(bx + i) * DIM + by + tx] = __float2half_rn(t[tx][i]);
}

// ---------------------------------------------------------------------------
// Kernel 1: Y = x @ W  (fp16 mma.sync m16n8k16 + ldmatrix + 3-stage cp.async)
// CTA tile 128x128, BK=32 (2 k16 steps), 256 thr = 8 warps (4m x 2n),
// warp tile 32x64. smem: 3 stages x (A 8KB + B 8KB) = 48KB.
// Row = 64B = 4 x 16B units; swizzle: unit(row,c) = row*4 + (c ^ ((row>>1)&3)).
// Prefetch for stage s issued ONLY after stage s is consumed (post-compute
// __syncthreads) — this ordering is load-bearing (R8 raced here).
// ---------------------------------------------------------------------------
#define STAGE_BYTES 16384
#define GEMM_SMEM   49152

__global__ void __launch_bounds__(256, 2) gemm_xw() {
    extern __shared__ char sm[];
    const uint32_t smb = smem_u32(sm);

    const int tid  = threadIdx.x;
    const int wid  = tid >> 5;
    const int lane = tid & 31;
    const int wm   = wid & 3;
    const int wn   = wid >> 2;

    const int m0 = blockIdx.y * 128;
    const int n0 = blockIdx.x * 128;

    // prefetch tile t (32 k-cols of halfs = 64B/row) into stage s
    #define PREF(t, s) do {                                                          \
        const int _kt = (t) * 32;                                                    \
        const uint32_t _ab = smb + (uint32_t)(s) * STAGE_BYTES;                      \
        const uint32_t _bb = _ab + 8192;                                             \
        _Pragma("unroll")                                                            \
        for (int _h = 0; _h < 2; _h++) {                                             \
            int _u = tid + _h * 256;                                                 \
            int _r = _u >> 2, _c = _u & 3;                                           \
            uint32_t _idx = (uint32_t)(_r * 4 + (_c ^ ((_r >> 1) & 3)));             \
            CP_ASYNC16(_ab + _idx * 16, g_xh + (size_t)(m0 + _r) * DIM + _kt + _c * 8); \
            CP_ASYNC16(_bb + _idx * 16, g_Wh + (size_t)(n0 + _r) * DIM + _kt + _c * 8); \
        }                                                                            \
    } while (0)

    float c[2][8][4];
#pragma unroll
    for (int i = 0; i < 2; i++)
#pragma unroll
        for (int j = 0; j < 8; j++)
#pragma unroll
            for (int k = 0; k < 4; k++) c[i][j][k] = 0.f;

    PREF(0, 0); CP_COMMIT();
    PREF(1, 1); CP_COMMIT();
    PREF(2, 2); CP_COMMIT();

    // ldmatrix lane geometry
    const int a_row14 = lane & 15;            // row within 16-row tile
    const int a_chalf = lane >> 4;            // 0: k 0-7, 1: k 8-15
    const int b_nrow  = (lane & 7) + ((lane >> 4) << 3);   // n row within 16-block
    const int b_chalf = (lane >> 3) & 1;                   // k half

#pragma unroll 1
    for (int t = 0; t < 16; t++) {
        CP_WAIT2();
        __syncthreads();
        const int s = t - (t / 3) * 3;
        const uint32_t Ab = smb + (uint32_t)s * STAGE_BYTES;
        const uint32_t Bb = Ab + 8192;

#pragma unroll
        for (int ks = 0; ks < 2; ks++) {
            uint32_t a[2][4], b[8][2];
#pragma unroll
            for (int mi = 0; mi < 2; mi++) {
                int row = wm * 32 + mi * 16 + a_row14;
                int cc  = ks * 2 + a_chalf;
                uint32_t addr = Ab + (uint32_t)(row * 4 + (cc ^ ((row >> 1) & 3))) * 16;
                LDMX4(a[mi][0], a[mi][1], a[mi][2], a[mi][3], addr);
            }
#pragma unroll
            for (int p = 0; p < 4; p++) {
                int n  = wn * 64 + p * 16 + b_nrow;
                int cc = ks * 2 + b_chalf;
                uint32_t addr = Bb + (uint32_t)(n * 4 + (cc ^ ((n >> 1) & 3))) * 16;
                LDMX4(b[2 * p][0], b[2 * p][1], b[2 * p + 1][0], b[2 * p + 1][1], addr);
            }
#pragma unroll
            for (int mi = 0; mi < 2; mi++)
#pragma unroll
                for (int ni = 0; ni < 8; ni++) {
                    asm volatile(
                        "mma.sync.aligned.m16n8k16.row.col.f32.f16.f16.f32 "
                        "{%0,%1,%2,%3}, {%4,%5,%6,%7}, {%8,%9}, {%0,%1,%2,%3};"
                        : "+f"(c[mi][ni][0]), "+f"(c[mi][ni][1]),
                          "+f"(c[mi][ni][2]), "+f"(c[mi][ni][3])
                        : "r"(a[mi][0]), "r"(a[mi][1]), "r"(a[mi][2]), "r"(a[mi][3]),
                          "r"(b[ni][0]), "r"(b[ni][1]));
                }
        }
        __syncthreads();             // stage s fully consumed
        if (t + 3 < 16) PREF(t + 3, s);
        CP_COMMIT();                 // commit every iter (empty ok) -> exact group accounting
    }

    // Epilogue: Y in fp32 and bf16
    const int g  = lane >> 2;
    const int tg = lane & 3;
#pragma unroll
    for (int mi = 0; mi < 2; mi++) {
#pragma unroll
        for (int ni = 0; ni < 8; ni++) {
            int row0 = m0 + wm * 32 + mi * 16 + g;
            int col  = n0 + wn * 64 + ni * 8 + tg * 2;
            float2 v01 = make_float2(c[mi][ni][0], c[mi][ni][1]);
            float2 v23 = make_float2(c[mi][ni][2], c[mi][ni][3]);
            *(float2*)(g_Yf + (size_t)row0 * DIM + col)       = v01;
            *(float2*)(g_Yf + (size_t)(row0 + 8) * DIM + col) = v23;
            __nv_bfloat162 h01, h23;
            h01.x = __float2bfloat16_rn(v01.x); h01.y = __float2bfloat16_rn(v01.y);
            h23.x = __float2bfloat16_rn(v23.x); h23.y = __float2bfloat16_rn(v23.y);
            *(__nv_bfloat162*)(g_Ybf + (size_t)row0 * DIM + col)       = h01;
            *(__nv_bfloat162*)(g_Ybf + (size_t)(row0 + 8) * DIM + col) = h23;
        }
    }
}

// ---------------------------------------------------------------------------
// Kernel 2: fused sparse aggregation + residual + bias + relu (R4, unchanged)
// ---------------------------------------------------------------------------
__global__ void __launch_bounds__(256) gcn_spmm(const float* __restrict__ A,
                                                const float* __restrict__ deg,
                                                const float* __restrict__ bias,
                                                float* __restrict__ out) {
    __shared__ uint16_t s_idx[8 * SEG_CAP];
    __shared__ int      s_cnt[8];
    __shared__ float    s_part[8 * DIM];

    const int row  = blockIdx.x;
    const int tid  = threadIdx.x;
    const int w    = tid >> 5;
    const int lane = tid & 31;
    const unsigned lml = (1u << lane) - 1u;

    // ---------------- Phase A: ballot compaction ----------------
    {
        const uint4* Ar = (const uint4*)(A + (size_t)row * N_NODES + w * 2048);
        int cnt = 0;
#pragma unroll 1
        for (int half = 0; half < 2; half++) {
            uint4 v[8];
#pragma unroll
            for (int k = 0; k < 8; k++)
                v[k] = __ldcs(Ar + (half * 8 + k) * 32 + lane);
#pragma unroll
            for (int k = 0; k < 8; k++) {
                unsigned nz  = v[k].x | v[k].y | v[k].z | v[k].w;
                unsigned any = __ballot_sync(0xFFFFFFFFu, nz != 0);
                if (any) {
                    int colbase = w * 2048 + ((half * 8 + k) * 32 + lane) * 4;
                    unsigned m;
                    m = __ballot_sync(0xFFFFFFFFu, v[k].x != 0);
                    if (v[k].x) { int p = cnt + __popc(m & lml); if (p < SEG_CAP) s_idx[w * SEG_CAP + p] = (uint16_t)(colbase + 0); }
                    cnt += __popc(m);
                    m = __ballot_sync(0xFFFFFFFFu, v[k].y != 0);
                    if (v[k].y) { int p = cnt + __popc(m & lml); if (p < SEG_CAP) s_idx[w * SEG_CAP + p] = (uint16_t)(colbase + 1); }
                    cnt += __popc(m);
                    m = __ballot_sync(0xFFFFFFFFu, v[k].z != 0);
                    if (v[k].z) { int p = cnt + __popc(m & lml); if (p < SEG_CAP) s_idx[w * SEG_CAP + p] = (uint16_t)(colbase + 2); }
                    cnt += __popc(m);
                    m = __ballot_sync(0xFFFFFFFFu, v[k].w != 0);
                    if (v[k].w) { int p = cnt + __popc(m & lml); if (p < SEG_CAP) s_idx[w * SEG_CAP + p] = (uint16_t)(colbase + 3); }
                    cnt += __popc(m);
                }
            }
        }
        if (lane == 0) s_cnt[w] = (cnt < SEG_CAP) ? cnt : SEG_CAP;
        __syncwarp();
    }

    // ---------------- Phase B: depth-2 pipelined gather ----------------
    float acc[16];
#pragma unroll
    for (int i = 0; i < 16; i++) acc[i] = 0.f;

    {
        const int n = s_cnt[w];
        const uint16_t* myidx = s_idx + w * SEG_CAP;
        uint4 pa[2], pb[2];
        if (n > 0) {
            const uint4* yp = (const uint4*)(g_Ybf + (size_t)myidx[0] * DIM);
            pa[0] = yp[lane]; pb[0] = yp[32 + lane];
        }
        if (n > 1) {
            const uint4* yp = (const uint4*)(g_Ybf + (size_t)myidx[1] * DIM);
            pa[1] = yp[lane]; pb[1] = yp[32 + lane];
        }
#pragma unroll 2
        for (int k = 0; k < n; k++) {
            uint4 ca = pa[k & 1];
            uint4 cb = pb[k & 1];
            if (k + 2 < n) {
                const uint4* yp = (const uint4*)(g_Ybf + (size_t)myidx[k + 2] * DIM);
                pa[k & 1] = yp[lane];
                pb[k & 1] = yp[32 + lane];
            }
            acc[0]  += bf_lo(ca.x); acc[1]  += bf_hi(ca.x);
            acc[2]  += bf_lo(ca.y); acc[3]  += bf_hi(ca.y);
            acc[4]  += bf_lo(ca.z); acc[5]  += bf_hi(ca.z);
            acc[6]  += bf_lo(ca.w); acc[7]  += bf_hi(ca.w);
            acc[8]  += bf_lo(cb.x); acc[9]  += bf_hi(cb.x);
            acc[10] += bf_lo(cb.y); acc[11] += bf_hi(cb.y);
            acc[12] += bf_lo(cb.z); acc[13] += bf_hi(cb.z);
            acc[14] += bf_lo(cb.w); acc[15] += bf_hi(cb.w);
        }
    }

    {
        float* p0 = s_part + w * DIM + 8 * lane;
        *(float4*)(p0 + 0)       = make_float4(acc[0], acc[1], acc[2], acc[3]);
        *(float4*)(p0 + 4)       = make_float4(acc[4], acc[5], acc[6], acc[7]);
        *(float4*)(p0 + 256)     = make_float4(acc[8], acc[9], acc[10], acc[11]);
        *(float4*)(p0 + 256 + 4) = make_float4(acc[12], acc[13], acc[14], acc[15]);
    }
    __syncthreads();

    {
        const int col = tid * 2;
        float a0 = 0.f, a1 = 0.f;
#pragma unroll
        for (int ww = 0; ww < 8; ww++) {
            float2 p = *(const float2*)(s_part + ww * DIM + col);
            a0 += p.x; a1 += p.y;
        }
        const float di = 1.0f / deg[row];
        float2 ys = *(const float2*)(g_Yf + (size_t)row * DIM + col);
        float2 bb = *(const float2*)(bias + col);
        float o0 = fmaxf(di * a0 + (1.0f + di) * ys.x + bb.x, 0.f);
        float o1 = fmaxf(di * a1 + (1.0f + di) * ys.y + bb.y, 0.f);
        *(float2*)(out + (size_t)row * DIM + col) = make_float2(o0, o1);
    }
}

// ---------------------------------------------------------------------------
extern "C" void kernel_launch(void* const* d_in, const int* in_sizes, int n_in,
                              void* d_out, int out_size) {
    const float *x = nullptr, *A = nullptr, *deg = nullptr, *W = nullptr, *b = nullptr;
    for (int i = 0; i < n_in; i++) {
        long long sz = (long long)in_sizes[i];
        if      (sz == (long long)N_NODES * N_NODES) A   = (const float*)d_in[i];
        else if (sz == (long long)N_NODES * DIM)     x   = (const float*)d_in[i];
        else if (sz == (long long)DIM * DIM)         W   = (const float*)d_in[i];
        else if (sz == (long long)N_NODES)           deg = (const float*)d_in[i];
        else if (sz == (long long)DIM)               b   = (const float*)d_in[i];
    }

    xh_kernel<<<(N_NODES * DIM) / (256 * 4), 256>>>(x);
    wt_kernel<<<dim3(16, 16), dim3(32, 8)>>>(W);
    gemm_xw<<<dim3(4, 128), 256, GEMM_SMEM>>>();
    gcn_spmm<<<N_NODES, 256>>>(A, deg, b, (float*)d_out);
}